// round 1
// baseline (speedup 1.0000x reference)
#include <cuda_runtime.h>
#include <cuda_bf16.h>

namespace {

constexpr int HH = 256, WW = 256, CIN = 64, COUT = 64, NB = 8;
constexpr int TH = 16, TW = 16;
constexpr int XS = 20;  // smem halo-tile row stride (18 cols + pad)

// Packed weights: per input channel i, 10 "taps" x 64 output channels.
// taps 0..8 = conv3x3 weights (ky*3+kx), tap 9 = combined quadratic matrix M[o][i].
__device__ float g_Wt[CIN][640];
__device__ float g_bias[COUT];  // linear_b + c (combined quadratic bias)

// grid = CIN blocks (one per input channel i), 64 threads (one per output channel o)
__global__ void precompute_kernel(const float* __restrict__ lw,
                                  const float* __restrict__ lb,
                                  const float* __restrict__ w2aw,
                                  const float* __restrict__ w2ab,
                                  const float* __restrict__ w2bw,
                                  const float* __restrict__ w2bb) {
    const int i = blockIdx.x;
    const int o = threadIdx.x;

    // conv taps: linear_w is [CO, CI, 3, 3]
#pragma unroll
    for (int t = 0; t < 9; t++)
        g_Wt[i][t * 64 + o] = lw[(o * 64 + i) * 9 + t];

    // M[o][i] = sum_q sum_m w2b[q][o][m] * w2a[q][m][i]
    float m = 0.f;
    for (int q = 0; q < 4; q++) {
        const float* wb = w2bw + q * 4096 + o * 64;
        const float* wa = w2aw + q * 4096 + i;
#pragma unroll 8
        for (int mm = 0; mm < 64; mm++)
            m = fmaf(wb[mm], wa[mm * 64], m);
    }
    g_Wt[i][9 * 64 + o] = m;

    if (i == 0) {
        // c[o] = sum_q ( w2b[q][o][:] . w2a_b[q][:] + w2b_b[q][o] )
        float c = 0.f;
        for (int q = 0; q < 4; q++) {
            const float* wb = w2bw + q * 4096 + o * 64;
            const float* ab = w2ab + q * 64;
            float h = 0.f;
#pragma unroll 8
            for (int mm = 0; mm < 64; mm++) h = fmaf(wb[mm], ab[mm], h);
            c += h + w2bb[q * 64 + o];
        }
        g_bias[o] = lb[o] + c;
    }
}

// Fused main kernel:
//   out[b,o,y,x] = sum_i [ sum_{3x3} w[o,i,t] * x_zeropad  +  M[o,i] * Sn_i(y,x) ] + bias[o]
//   Sn_i = ( (circ 3x3 sum of x)^2 + circ 3x3 sum of x^2 ) / 90
// Block: 256 threads over a 16x16 pixel tile; thread = (ocg = tid>>5 -> 8 output
// channels) x (pg = tid&31 -> 8-pixel row segment). 64 fp32 accumulators/thread.
__global__ __launch_bounds__(256, 1)
void volterra_kernel(const float* __restrict__ x, float* __restrict__ out) {
    const int b = blockIdx.z;
    const int ty0 = blockIdx.y * TH;
    const int tx0 = blockIdx.x * TW;
    const int tid = (int)threadIdx.x;
    const int ocg = tid >> 5;        // 0..7 : output-channel group (8 ch)
    const int pg = tid & 31;         // 0..31 : pixel group (8 px each)
    const int py = pg >> 1;          // tile row 0..15
    const int pxb = (pg & 1) * 8;    // tile col base 0 or 8
    const int gy = ty0 + py;         // global row of this thread's pixels

    __shared__ float sx[18 * XS];    // circular halo tile for channel i
    __shared__ float sw[640];        // packed weights for channel i

    float acc[8][8];
#pragma unroll
    for (int a = 0; a < 8; a++)
#pragma unroll
        for (int k = 0; k < 8; k++) acc[a][k] = 0.f;

    // zero-pad row masks (conv only; Sn stays circular)
    const float rm0 = (gy != 0) ? 1.f : 0.f;
    const float rm2 = (gy != HH - 1) ? 1.f : 0.f;

    const float* xb = x + ((size_t)b << 22);  // b * CIN * H * W

#pragma unroll 1
    for (int i = 0; i < CIN; i++) {
        __syncthreads();  // previous iteration's smem reads done
        const float* xc = xb + ((size_t)i << 16);

        // 18x18 halo tile, circular wrap (H=W=256 -> & 255)
        for (int idx = tid; idx < 18 * 18; idx += 256) {
            int r = idx / 18;
            int c = idx - r * 18;
            int yy = (ty0 - 1 + r) & 255;
            int xx = (tx0 - 1 + c) & 255;
            sx[r * XS + c] = xc[(yy << 8) + xx];
        }
        {
            const float* wrow = g_Wt[i];
            sw[tid] = wrow[tid];
            sw[tid + 256] = wrow[tid + 256];
            if (tid < 128) sw[tid + 512] = wrow[tid + 512];
        }
        __syncthreads();

        // this thread's 8 output channels x 10 taps -> registers (broadcast LDS)
        float wr[8][10];
#pragma unroll
        for (int oo = 0; oo < 8; oo++)
#pragma unroll
            for (int t = 0; t < 10; t++)
                wr[oo][t] = sw[t * 64 + (ocg * 8 + oo)];

#pragma unroll
        for (int k = 0; k < 8; k++) {
            const int px = pxb + k;
            const float* sp = sx + py * XS + px;
            float v00 = sp[0],          v01 = sp[1],            v02 = sp[2];
            float v10 = sp[XS],         v11 = sp[XS + 1],       v12 = sp[XS + 2];
            float v20 = sp[2 * XS],     v21 = sp[2 * XS + 1],   v22 = sp[2 * XS + 2];

            // circular 3x3 sums -> Sn
            float s = ((v00 + v01) + (v02 + v10)) +
                      ((v11 + v12) + (v20 + v21)) + v22;
            float s2 = v00 * v00;
            s2 = fmaf(v01, v01, s2); s2 = fmaf(v02, v02, s2);
            s2 = fmaf(v10, v10, s2); s2 = fmaf(v11, v11, s2);
            s2 = fmaf(v12, v12, s2); s2 = fmaf(v20, v20, s2);
            s2 = fmaf(v21, v21, s2); s2 = fmaf(v22, v22, s2);
            const float Sn = fmaf(s, s, s2) * (1.0f / 90.0f);

            // zero-pad column masks for conv taps
            const int gx = tx0 + px;
            const float cm0 = (gx != 0) ? 1.f : 0.f;
            const float cm2 = (gx != WW - 1) ? 1.f : 0.f;
            const float c00 = v00 * rm0 * cm0, c01 = v01 * rm0, c02 = v02 * rm0 * cm2;
            const float c10 = v10 * cm0,       c11 = v11,       c12 = v12 * cm2;
            const float c20 = v20 * rm2 * cm0, c21 = v21 * rm2, c22 = v22 * rm2 * cm2;

#pragma unroll
            for (int oo = 0; oo < 8; oo++) {
                float a0 = acc[oo][k];
                a0 = fmaf(wr[oo][0], c00, a0);
                a0 = fmaf(wr[oo][1], c01, a0);
                a0 = fmaf(wr[oo][2], c02, a0);
                a0 = fmaf(wr[oo][3], c10, a0);
                a0 = fmaf(wr[oo][4], c11, a0);
                a0 = fmaf(wr[oo][5], c12, a0);
                a0 = fmaf(wr[oo][6], c20, a0);
                a0 = fmaf(wr[oo][7], c21, a0);
                a0 = fmaf(wr[oo][8], c22, a0);
                a0 = fmaf(wr[oo][9], Sn, a0);
                acc[oo][k] = a0;
            }
        }
    }

    // epilogue: + bias, vectorized stores (tx0+pxb is 8-aligned -> 16B aligned)
#pragma unroll
    for (int oo = 0; oo < 8; oo++) {
        const int o = ocg * 8 + oo;
        const float bo = g_bias[o];
        float4 r0 = make_float4(acc[oo][0] + bo, acc[oo][1] + bo,
                                acc[oo][2] + bo, acc[oo][3] + bo);
        float4 r1 = make_float4(acc[oo][4] + bo, acc[oo][5] + bo,
                                acc[oo][6] + bo, acc[oo][7] + bo);
        float4* dst = (float4*)(out + (((size_t)(b * COUT + o)) << 16) +
                                (gy << 8) + tx0 + pxb);
        dst[0] = r0;
        dst[1] = r1;
    }
}

}  // namespace

extern "C" void kernel_launch(void* const* d_in, const int* in_sizes, int n_in,
                              void* d_out, int out_size) {
    (void)in_sizes; (void)n_in; (void)out_size;
    const float* x    = (const float*)d_in[0];
    const float* lw   = (const float*)d_in[1];
    const float* lb   = (const float*)d_in[2];
    const float* w2aw = (const float*)d_in[3];
    const float* w2ab = (const float*)d_in[4];
    const float* w2bw = (const float*)d_in[5];
    const float* w2bb = (const float*)d_in[6];
    float* out = (float*)d_out;

    precompute_kernel<<<CIN, 64>>>(lw, lb, w2aw, w2ab, w2bw, w2bb);
    volterra_kernel<<<dim3(WW / TW, HH / TH, NB), 256>>>(x, out);
}